// round 7
// baseline (speedup 1.0000x reference)
#include <cuda_runtime.h>

#define B_SZ 8192
#define T_SZ 32
#define NBLK 257
#define NTHR 256

// Static device scratch
__device__ float d_Tp[27 * 20];                 // [mx][k], k = mh*2+j, pads 0
__device__ float d_To[9];                       // readout tensor
__device__ float4 d_S4[T_SZ * 5 * B_SZ];        // [t][q][b] float4 (21MB)
__device__ unsigned g_ticket = 0;               // monotonic, never reset
__device__ unsigned g_tp = 0;                   // T-ready epochs
__device__ unsigned g_done = 0;                 // phase1-done block count

__device__ __forceinline__ float2 cmul(float2 a, float2 b) {
    return make_float2(a.x * b.x - a.y * b.y, a.x * b.y + a.y * b.x);
}
__device__ __forceinline__ unsigned long long fma2(unsigned long long a,
                                                   unsigned long long b,
                                                   unsigned long long c) {
    unsigned long long d;
    asm("fma.rn.f32x2 %0, %1, %2, %3;" : "=l"(d) : "l"(a), "l"(b), "l"(c));
    return d;
}
__device__ __forceinline__ unsigned long long pk2(float x) {
    unsigned long long r;
    asm("mov.b64 %0, {%1, %1};" : "=l"(r) : "f"(x));
    return r;
}
__device__ __forceinline__ void cpa16(void* smem, const void* gmem) {
    unsigned s = (unsigned)__cvta_generic_to_shared(smem);
    asm volatile("cp.async.cg.shared.global [%0], [%1], 16;"
                 :: "r"(s), "l"(gmem) : "memory");
}
__device__ __forceinline__ unsigned ld_acq(unsigned* p) {
    unsigned v;
    asm volatile("ld.acquire.gpu.u32 %0, [%1];" : "=r"(v) : "l"(p));
    return v;
}

__global__ void __launch_bounds__(NTHR, 2) mega_kernel(
        const float* __restrict__ x_seq,
        const float* __restrict__ wrec,
        const float* __restrict__ wout,
        float* __restrict__ out) {
    __shared__ float s_Ts[540];
    __shared__ __align__(16) char s_big[20608];
    __shared__ unsigned s_epoch;

    const int tid = threadIdx.x;
    const int blk = blockIdx.x;

    if (tid == 0) {
        unsigned ticket = atomicAdd(&g_ticket, 1u);
        s_epoch = ticket / NBLK;
    }
    __syncthreads();
    const unsigned epoch = s_epoch;

    // ======================= block 256: T precompute =======================
    if (blk == 256) {
        float*  UsR = (float*)s_big;             // [32][33]
        float*  UsI = UsR + 32 * 33;             // [32][33]
        float*  Ms  = UsI + 32 * 33;             // [2][32][33]
        float2* G   = (float2*)(Ms + 2 * 32 * 33);  // [10][4]

        if (tid < 10) {
            float phi = wrec[tid * 3 + 0];
            float th  = wrec[tid * 3 + 1];
            float om  = wrec[tid * 3 + 2];
            float s, c, sa, ca, sb, cb;
            __sincosf(0.5f * th, &s, &c);
            __sincosf(0.5f * (phi + om), &sa, &ca);
            __sincosf(0.5f * (phi - om), &sb, &cb);
            G[tid * 4 + 0] = make_float2( c * ca, -c * sa);
            G[tid * 4 + 1] = make_float2(-s * cb, -s * sb);
            G[tid * 4 + 2] = make_float2( s * cb, -s * sb);
            G[tid * 4 + 3] = make_float2( c * ca,  c * sa);
        }
        // U = I (4 entries/thread)
#pragma unroll
        for (int r = 0; r < 4; r++) {
            int idx = r * 256 + tid;
            int row = idx >> 5, col = idx & 31;
            UsR[row * 33 + col] = (row == col) ? 1.f : 0.f;
            UsI[row * 33 + col] = 0.f;
        }
        __syncthreads();

#pragma unroll
        for (int l = 0; l < 2; l++) {
#pragma unroll
            for (int w = 0; w < 5; w++) {
                int mask = 1 << (4 - w);
                int low = mask - 1;
                float2 r00 = G[(l * 5 + w) * 4 + 0], r01 = G[(l * 5 + w) * 4 + 1];
                float2 r10 = G[(l * 5 + w) * 4 + 2], r11 = G[(l * 5 + w) * 4 + 3];
#pragma unroll
                for (int r = 0; r < 2; r++) {
                    int idx = r * 256 + tid;
                    int col = idx & 31, p = idx >> 5;
                    int i0 = ((p & ~low) << 1) | (p & low);
                    int i1 = i0 | mask;
                    float2 a0 = make_float2(UsR[i0 * 33 + col], UsI[i0 * 33 + col]);
                    float2 a1 = make_float2(UsR[i1 * 33 + col], UsI[i1 * 33 + col]);
                    float2 n0 = cmul(r00, a0), u01 = cmul(r01, a1);
                    n0.x += u01.x; n0.y += u01.y;
                    float2 n1 = cmul(r10, a0), u11 = cmul(r11, a1);
                    n1.x += u11.x; n1.y += u11.y;
                    UsR[i0 * 33 + col] = n0.x; UsI[i0 * 33 + col] = n0.y;
                    UsR[i1 * 33 + col] = n1.x; UsI[i1 * 33 + col] = n1.y;
                }
                __syncthreads();
            }
            // CNOT ring (range l+1) fused into one permutation
            {
                float vr[4], vi[4];
                int drow[4], dcol[4];
#pragma unroll
                for (int r = 0; r < 4; r++) {
                    int idx = r * 256 + tid;
                    int row = idx >> 5, col = idx & 31;
                    int rr = l + 1;
                    int j = row;
#pragma unroll
                    for (int w = 4; w >= 0; w--) {
                        int cm = 1 << (4 - w);
                        int tm = 1 << (4 - ((w + rr) % 5));
                        if (j & cm) j ^= tm;
                    }
                    vr[r] = UsR[j * 33 + col];
                    vi[r] = UsI[j * 33 + col];
                    drow[r] = row; dcol[r] = col;
                }
                __syncthreads();
#pragma unroll
                for (int r = 0; r < 4; r++) {
                    UsR[drow[r] * 33 + dcol[r]] = vr[r];
                    UsI[drow[r] * 33 + dcol[r]] = vi[r];
                }
                __syncthreads();
            }
        }

        // M (4 (s,t) pairs/thread, both j)
#pragma unroll
        for (int r = 0; r < 4; r++) {
            int idx = r * 256 + tid;
            int s = idx >> 5, t = idx & 31;
            float m0 = 0.f, m1 = 0.f;
#pragma unroll
            for (int k = 0; k < 32; k++) {
                float ar = UsR[k * 33 + s], ai = UsI[k * 33 + s];
                float br = UsR[k * 33 + t], bi = UsI[k * 33 + t];
                float re = ar * br + ai * bi;
                m0 += ((k >> 1) & 1) ? -re : re;
                m1 += (k & 1) ? -re : re;
            }
            Ms[0 * 1056 + s * 33 + t] = m0;
            Ms[1 * 1056 + s * 33 + t] = m1;
        }
        __syncthreads();

        // T tensor -> d_Tp (2 entries/thread) + pads
#pragma unroll
        for (int r = 0; r < 2; r++) {
            int idx = r * 256 + tid;
            if (idx < 486) {
                int j = idx / 243, m = idx % 243;
                int dg[5];
                int mm = m;
#pragma unroll
                for (int w = 4; w >= 0; w--) { dg[w] = mm % 3; mm /= 3; }
                int emask = 0, xmask = 0;
#pragma unroll
                for (int w = 0; w < 5; w++) {
                    if (dg[w] == 1) emask |= 1 << (4 - w);
                    if (dg[w] == 2) xmask |= 1 << (4 - w);
                }
                float sum = 0.f;
#pragma unroll
                for (int u = 0; u < 32; u++) {
                    float sgn = (__popc(u & emask) & 1) ? -1.f : 1.f;
                    sum += sgn * Ms[j * 1056 + u * 33 + (u ^ xmask)];
                }
                d_Tp[(m / 9) * 20 + (m % 9) * 2 + j] = sum * (1.f / 32.f);
            }
        }
        if (tid < 54) {
            d_Tp[(tid >> 1) * 20 + 18 + (tid & 1)] = 0.f;
        }

        __threadfence();
        __syncthreads();
        if (tid == 0) {
            atomicAdd(&g_tp, 1u);
            atomicAdd(&g_done, 1u);
        }
        return;
    }

    // ============== block 0, lanes 0-8: readout tensor To ==============
    if (blk == 0 && tid < 9) {
        int m = tid;
        float2 V[4][4];
#pragma unroll
        for (int c2 = 0; c2 < 4; c2++)
#pragma unroll
            for (int r2 = 0; r2 < 4; r2++)
                V[c2][r2] = make_float2(c2 == r2 ? 1.f : 0.f, 0.f);
#pragma unroll
        for (int l = 0; l < 2; l++) {
#pragma unroll
            for (int w = 0; w < 2; w++) {
                float phi = wout[(l * 2 + w) * 3 + 0];
                float th  = wout[(l * 2 + w) * 3 + 1];
                float om  = wout[(l * 2 + w) * 3 + 2];
                float s, c, sa, ca, sb, cb;
                __sincosf(0.5f * th, &s, &c);
                __sincosf(0.5f * (phi + om), &sa, &ca);
                __sincosf(0.5f * (phi - om), &sb, &cb);
                float2 r00 = make_float2( c * ca, -c * sa);
                float2 r01 = make_float2(-s * cb, -s * sb);
                float2 r10 = make_float2( s * cb, -s * sb);
                float2 r11 = make_float2( c * ca,  c * sa);
                int mask = 1 << (1 - w);
#pragma unroll
                for (int col = 0; col < 4; col++) {
#pragma unroll
                    for (int i0 = 0; i0 < 4; i0++) {
                        if (i0 & mask) continue;
                        int i1 = i0 | mask;
                        float2 a0 = V[col][i0], a1 = V[col][i1];
                        float2 n0 = cmul(r00, a0), u01 = cmul(r01, a1);
                        n0.x += u01.x; n0.y += u01.y;
                        float2 n1 = cmul(r10, a0), u11 = cmul(r11, a1);
                        n1.x += u11.x; n1.y += u11.y;
                        V[col][i0] = n0;
                        V[col][i1] = n1;
                    }
                }
            }
#pragma unroll
            for (int w = 0; w < 2; w++) {
                int cm = 1 << (1 - w), tm = 1 << (1 - ((w + 1) & 1));
#pragma unroll
                for (int col = 0; col < 4; col++)
#pragma unroll
                    for (int row = 0; row < 4; row++)
                        if ((row & cm) && !(row & tm)) {
                            float2 a = V[col][row], b2 = V[col][row | tm];
                            V[col][row] = b2;
                            V[col][row | tm] = a;
                        }
            }
        }
        float Mo[4][4];
#pragma unroll
        for (int s = 0; s < 4; s++)
#pragma unroll
            for (int t = 0; t < 4; t++) {
                float acc = 0.f;
#pragma unroll
                for (int k = 0; k < 4; k++) {
                    float2 vs = V[s][k], vt = V[t][k];
                    float re = vs.x * vt.x + vs.y * vt.y;
                    acc += ((k >> 1) & 1) ? -re : re;
                }
                Mo[s][t] = acc;
            }
        int d0 = m / 3, d1 = m % 3;
        int emask = (d0 == 1 ? 2 : 0) | (d1 == 1 ? 1 : 0);
        int xmask = (d0 == 2 ? 2 : 0) | (d1 == 2 ? 1 : 0);
        float sum = 0.f;
#pragma unroll
        for (int u = 0; u < 4; u++) {
            float sgn = (__popc(u & emask) & 1) ? -1.f : 1.f;
            sum += sgn * Mo[u][u ^ xmask];
        }
        d_To[m] = sum * 0.25f;
    }

    // ======================= wait for T, load Ts =======================
    if (tid == 0) {
        while (ld_acq(&g_tp) < epoch + 1) { __nanosleep(32); }
    }
    __syncthreads();
    for (int i = tid; i < 540; i += NTHR) s_Ts[i] = d_Tp[i];
    __syncthreads();

    // ======================= phase 1: 4 elements/thread =======================
    unsigned tbase = (unsigned)__cvta_generic_to_shared(s_Ts);
#pragma unroll
    for (int ii = 0; ii < 4; ii++) {
        int e = blk * 1024 + ii * 256 + tid;
        int b = e & (B_SZ - 1);
        int t = e >> 13;
        const float* xp = x_seq + ((size_t)t * B_SZ + b) * 3;
        float x0 = xp[0], x1 = xp[1], x2 = xp[2];
        float s0, c0, s1, c1, s2, c2;
        __sincosf(x0, &s0, &c0);
        __sincosf(x1, &s1, &c1);
        __sincosf(x2, &s2, &c2);
        float g0[3] = {1.f, c0, s0};
        float g1[3] = {1.f, c1, s1};
        float g2[3] = {1.f, c2, s2};

        unsigned long long acc[10];
#pragma unroll
        for (int q = 0; q < 10; q++) acc[q] = 0ull;

#pragma unroll
        for (int m0 = 0; m0 < 3; m0++) {
#pragma unroll
            for (int m1 = 0; m1 < 3; m1++) {
                float p01 = g0[m0] * g1[m1];
#pragma unroll
                for (int m2 = 0; m2 < 3; m2++) {
                    float p = p01 * g2[m2];
                    unsigned long long p2 = pk2(p);
                    int mx = (m0 * 3 + m1) * 3 + m2;
                    unsigned ra = tbase + mx * 80;
#pragma unroll
                    for (int q = 0; q < 5; q++) {
                        unsigned long long t0, t1;
                        asm volatile("ld.shared.v2.b64 {%0,%1}, [%2];"
                                     : "=l"(t0), "=l"(t1) : "r"(ra + q * 16));
                        acc[2 * q]     = fma2(p2, t0, acc[2 * q]);
                        acc[2 * q + 1] = fma2(p2, t1, acc[2 * q + 1]);
                    }
                }
            }
        }

#pragma unroll
        for (int q = 0; q < 5; q++) {
            float l0, h0v, l1, h1v;
            asm("mov.b64 {%0,%1}, %2;" : "=f"(l0), "=f"(h0v) : "l"(acc[2 * q]));
            asm("mov.b64 {%0,%1}, %2;" : "=f"(l1), "=f"(h1v) : "l"(acc[2 * q + 1]));
            d_S4[((size_t)t * 5 + q) * B_SZ + b] = make_float4(l0, h0v, l1, h1v);
        }
    }

    __threadfence();
    __syncthreads();
    if (tid == 0) atomicAdd(&g_done, 1u);

    // ======================= grid barrier =======================
    if (tid == 0) {
        unsigned target = (epoch + 1) * NBLK;
        while (ld_acq(&g_done) < target) { __nanosleep(32); }
    }
    __syncthreads();

    // ======================= phase 2: warp 0, 32 b's per block =======================
    if (tid < 32) {
        float4 (*sbuf)[5][32] = (float4(*)[5][32])s_big;   // [8][5][32]
        const int b = blk * 32 + tid;

#pragma unroll
        for (int t = 0; t < 7; t++) {
#pragma unroll
            for (int q = 0; q < 5; q++)
                cpa16(&sbuf[t][q][tid], &d_S4[((size_t)t * 5 + q) * B_SZ + b]);
            asm volatile("cp.async.commit_group;" ::: "memory");
        }

        float h0 = 0.f, h1 = 0.f;
#pragma unroll
        for (int t = 0; t < T_SZ; t++) {
            asm volatile("cp.async.wait_group 6;" ::: "memory");
            float4 v[5];
#pragma unroll
            for (int q = 0; q < 5; q++) v[q] = sbuf[t & 7][q][tid];

            if (t + 7 < T_SZ) {
#pragma unroll
                for (int q = 0; q < 5; q++)
                    cpa16(&sbuf[(t + 7) & 7][q][tid],
                          &d_S4[((size_t)(t + 7) * 5 + q) * B_SZ + b]);
            }
            asm volatile("cp.async.commit_group;" ::: "memory");

            float Sc[20];
#pragma unroll
            for (int q = 0; q < 5; q++) {
                Sc[4 * q + 0] = v[q].x;
                Sc[4 * q + 1] = v[q].y;
                Sc[4 * q + 2] = v[q].z;
                Sc[4 * q + 3] = v[q].w;
            }
            float sh0, ch0, sh1, ch1;
            __sincosf(h0, &sh0, &ch0);
            __sincosf(h1, &sh1, &ch1);
            float Q[9];
            Q[0] = 1.f;        Q[1] = ch1;        Q[2] = sh1;
            Q[3] = ch0;        Q[4] = ch0 * ch1;  Q[5] = ch0 * sh1;
            Q[6] = sh0;        Q[7] = sh0 * ch1;  Q[8] = sh0 * sh1;
            float a0 = 0.f, a1 = 0.f;
#pragma unroll
            for (int mh = 0; mh < 9; mh++) {
                a0 += Sc[2 * mh] * Q[mh];
                a1 += Sc[2 * mh + 1] * Q[mh];
            }
            h0 = a0;
            h1 = a1;
        }

        float To[9];
#pragma unroll
        for (int i = 0; i < 9; i++) To[i] = d_To[i];
        float sh0, ch0, sh1, ch1;
        __sincosf(h0, &sh0, &ch0);
        __sincosf(h1, &sh1, &ch1);
        float Q[9] = {1.f, ch1, sh1, ch0, ch0 * ch1, ch0 * sh1,
                      sh0, sh0 * ch1, sh0 * sh1};
        float r = 0.f;
#pragma unroll
        for (int m = 0; m < 9; m++) r += To[m] * Q[m];
        out[b] = r;
    }
}

// ---------------------------------------------------------------------------
extern "C" void kernel_launch(void* const* d_in, const int* in_sizes, int n_in,
                              void* d_out, int out_size) {
    const float* x_seq = nullptr;
    const float* w_rec = nullptr;
    const float* w_out = nullptr;
    for (int i = 0; i < n_in; i++) {
        if (in_sizes[i] == T_SZ * B_SZ * 3) x_seq = (const float*)d_in[i];
        else if (in_sizes[i] == 30)         w_rec = (const float*)d_in[i];
        else if (in_sizes[i] == 12)         w_out = (const float*)d_in[i];
    }
    float* out = (float*)d_out;

    mega_kernel<<<NBLK, NTHR>>>(x_seq, w_rec, w_out, out);
}

// round 8
// speedup vs baseline: 3.7361x; 3.7361x over previous
#include <cuda_runtime.h>

#define B_SZ 8192
#define T_SZ 32

// Static device scratch
__device__ float d_Tp[27 * 20];                 // [mx][k], k = mh*2+j, pads 0
__device__ float d_To[9];                       // readout tensor
__device__ float4 d_S4[T_SZ * 5 * B_SZ];        // [t][q][b] float4 (21MB)

__device__ __forceinline__ float2 cmul(float2 a, float2 b) {
    return make_float2(a.x * b.x - a.y * b.y, a.x * b.y + a.y * b.x);
}
__device__ __forceinline__ unsigned long long fma2(unsigned long long a,
                                                   unsigned long long b,
                                                   unsigned long long c) {
    unsigned long long d;
    asm("fma.rn.f32x2 %0, %1, %2, %3;" : "=l"(d) : "l"(a), "l"(b), "l"(c));
    return d;
}
__device__ __forceinline__ unsigned long long pk2(float x) {
    unsigned long long r;
    asm("mov.b64 %0, {%1, %1};" : "=l"(r) : "f"(x));
    return r;
}
__device__ __forceinline__ void cpa16(void* smem, const void* gmem) {
    unsigned s = (unsigned)__cvta_generic_to_shared(smem);
    asm volatile("cp.async.cg.shared.global [%0], [%1], 16;"
                 :: "r"(s), "l"(gmem) : "memory");
}
__device__ __forceinline__ void pdl_trigger() {
    asm volatile("griddepcontrol.launch_dependents;");
}
__device__ __forceinline__ void pdl_wait() {
    asm volatile("griddepcontrol.wait;" ::: "memory");
}

// ---------------------------------------------------------------------------
// Precompute (1 block, 1024 threads). Triggers dependent launch at entry so
// phase1 fills the chip while this latency-bound block runs.
// ---------------------------------------------------------------------------
__global__ void __launch_bounds__(1024) precompute_kernel(const float* __restrict__ wrec,
                                                          const float* __restrict__ wout) {
    pdl_trigger();

    __shared__ float2 G[10][4];
    __shared__ float UsR[32][33];
    __shared__ float UsI[32][33];
    __shared__ float Ms[2][32][33];
    const int tid = threadIdx.x;

    if (tid < 10) {
        float phi = wrec[tid * 3 + 0];
        float th  = wrec[tid * 3 + 1];
        float om  = wrec[tid * 3 + 2];
        float s, c, sa, ca, sb, cb;
        __sincosf(0.5f * th, &s, &c);
        __sincosf(0.5f * (phi + om), &sa, &ca);
        __sincosf(0.5f * (phi - om), &sb, &cb);
        G[tid][0] = make_float2( c * ca, -c * sa);
        G[tid][1] = make_float2(-s * cb, -s * sb);
        G[tid][2] = make_float2( s * cb, -s * sb);
        G[tid][3] = make_float2( c * ca,  c * sa);
    }
    {
        int row = tid >> 5, col = tid & 31;
        UsR[row][col] = (row == col) ? 1.f : 0.f;
        UsI[row][col] = 0.f;
    }
    __syncthreads();

#pragma unroll
    for (int l = 0; l < 2; l++) {
#pragma unroll
        for (int w = 0; w < 5; w++) {
            if (tid < 512) {
                int col = tid & 31, p = tid >> 5;
                int mask = 1 << (4 - w);
                int low = mask - 1;
                int i0 = ((p & ~low) << 1) | (p & low);
                int i1 = i0 | mask;
                float2 r00 = G[l * 5 + w][0], r01 = G[l * 5 + w][1];
                float2 r10 = G[l * 5 + w][2], r11 = G[l * 5 + w][3];
                float2 a0 = make_float2(UsR[i0][col], UsI[i0][col]);
                float2 a1 = make_float2(UsR[i1][col], UsI[i1][col]);
                float2 n0 = cmul(r00, a0), u01 = cmul(r01, a1);
                n0.x += u01.x; n0.y += u01.y;
                float2 n1 = cmul(r10, a0), u11 = cmul(r11, a1);
                n1.x += u11.x; n1.y += u11.y;
                UsR[i0][col] = n0.x; UsI[i0][col] = n0.y;
                UsR[i1][col] = n1.x; UsI[i1][col] = n1.y;
            }
            __syncthreads();
        }
        {
            int row = tid >> 5, col = tid & 31;
            int rr = l + 1;
            int j = row;
#pragma unroll
            for (int w = 4; w >= 0; w--) {
                int cm = 1 << (4 - w);
                int tm = 1 << (4 - ((w + rr) % 5));
                if (j & cm) j ^= tm;
            }
            float vr = UsR[j][col], vi = UsI[j][col];
            __syncthreads();
            UsR[row][col] = vr;
            UsI[row][col] = vi;
            __syncthreads();
        }
    }

    {
        int s = tid >> 5, t = tid & 31;
        float m0 = 0.f, m1 = 0.f;
#pragma unroll
        for (int k = 0; k < 32; k++) {
            float ar = UsR[k][s], ai = UsI[k][s];
            float br = UsR[k][t], bi = UsI[k][t];
            float re = ar * br + ai * bi;
            m0 += ((k >> 1) & 1) ? -re : re;
            m1 += (k & 1) ? -re : re;
        }
        Ms[0][s][t] = m0;
        Ms[1][s][t] = m1;
    }
    __syncthreads();

    if (tid < 486) {
        int j = tid / 243, m = tid % 243;
        int dg[5];
        int mm = m;
#pragma unroll
        for (int w = 4; w >= 0; w--) { dg[w] = mm % 3; mm /= 3; }
        int emask = 0, xmask = 0;
#pragma unroll
        for (int w = 0; w < 5; w++) {
            if (dg[w] == 1) emask |= 1 << (4 - w);
            if (dg[w] == 2) xmask |= 1 << (4 - w);
        }
        float sum = 0.f;
#pragma unroll
        for (int u = 0; u < 32; u++) {
            float sgn = (__popc(u & emask) & 1) ? -1.f : 1.f;
            sum += sgn * Ms[j][u][u ^ xmask];
        }
        d_Tp[(m / 9) * 20 + (m % 9) * 2 + j] = sum * (1.f / 32.f);
    }
    if (tid >= 640 && tid < 640 + 54) {
        int i = tid - 640;
        d_Tp[(i >> 1) * 20 + 18 + (i & 1)] = 0.f;
    }

    if (tid >= 512 && tid < 521) {
        int m = tid - 512;
        float2 V[4][4];
#pragma unroll
        for (int c2 = 0; c2 < 4; c2++)
#pragma unroll
            for (int r2 = 0; r2 < 4; r2++)
                V[c2][r2] = make_float2(c2 == r2 ? 1.f : 0.f, 0.f);
#pragma unroll
        for (int l = 0; l < 2; l++) {
#pragma unroll
            for (int w = 0; w < 2; w++) {
                float phi = wout[(l * 2 + w) * 3 + 0];
                float th  = wout[(l * 2 + w) * 3 + 1];
                float om  = wout[(l * 2 + w) * 3 + 2];
                float s, c, sa, ca, sb, cb;
                __sincosf(0.5f * th, &s, &c);
                __sincosf(0.5f * (phi + om), &sa, &ca);
                __sincosf(0.5f * (phi - om), &sb, &cb);
                float2 r00 = make_float2( c * ca, -c * sa);
                float2 r01 = make_float2(-s * cb, -s * sb);
                float2 r10 = make_float2( s * cb, -s * sb);
                float2 r11 = make_float2( c * ca,  c * sa);
                int mask = 1 << (1 - w);
#pragma unroll
                for (int col = 0; col < 4; col++) {
#pragma unroll
                    for (int i0 = 0; i0 < 4; i0++) {
                        if (i0 & mask) continue;
                        int i1 = i0 | mask;
                        float2 a0 = V[col][i0], a1 = V[col][i1];
                        float2 n0 = cmul(r00, a0), u01 = cmul(r01, a1);
                        n0.x += u01.x; n0.y += u01.y;
                        float2 n1 = cmul(r10, a0), u11 = cmul(r11, a1);
                        n1.x += u11.x; n1.y += u11.y;
                        V[col][i0] = n0;
                        V[col][i1] = n1;
                    }
                }
            }
#pragma unroll
            for (int w = 0; w < 2; w++) {
                int cm = 1 << (1 - w), tm = 1 << (1 - ((w + 1) & 1));
#pragma unroll
                for (int col = 0; col < 4; col++)
#pragma unroll
                    for (int row = 0; row < 4; row++)
                        if ((row & cm) && !(row & tm)) {
                            float2 a = V[col][row], b2 = V[col][row | tm];
                            V[col][row] = b2;
                            V[col][row | tm] = a;
                        }
            }
        }
        float Mo[4][4];
#pragma unroll
        for (int s = 0; s < 4; s++)
#pragma unroll
            for (int t = 0; t < 4; t++) {
                float acc = 0.f;
#pragma unroll
                for (int k = 0; k < 4; k++) {
                    float2 vs = V[s][k], vt = V[t][k];
                    float re = vs.x * vt.x + vs.y * vt.y;
                    acc += ((k >> 1) & 1) ? -re : re;
                }
                Mo[s][t] = acc;
            }
        int d0 = m / 3, d1 = m % 3;
        int emask = (d0 == 1 ? 2 : 0) | (d1 == 1 ? 1 : 0);
        int xmask = (d0 == 2 ? 2 : 0) | (d1 == 2 ? 1 : 0);
        float sum = 0.f;
#pragma unroll
        for (int u = 0; u < 4; u++) {
            float sgn = (__popc(u & emask) & 1) ? -1.f : 1.f;
            sum += sgn * Mo[u][u ^ xmask];
        }
        d_To[m] = sum * 0.25f;
    }
}

// ---------------------------------------------------------------------------
// Phase 1 (PDL): T-independent prework (x loads, sincos, P monomials) BEFORE
// griddepcontrol.wait; T contraction after.
// ---------------------------------------------------------------------------
__global__ void __launch_bounds__(256) phase1_kernel(const float* __restrict__ x_seq) {
    __shared__ __align__(16) float Ts[27 * 20];
    const int tid = threadIdx.x;

    int e = blockIdx.x * 256 + tid;
    int b = e & (B_SZ - 1);
    int t = e >> 13;

    // ---- prework (overlaps with precompute) ----
    const float* xp = x_seq + ((size_t)t * B_SZ + b) * 3;
    float x0 = xp[0], x1 = xp[1], x2 = xp[2];
    float s0, c0, s1, c1, s2, c2;
    __sincosf(x0, &s0, &c0);
    __sincosf(x1, &s1, &c1);
    __sincosf(x2, &s2, &c2);
    float g0[3] = {1.f, c0, s0};
    float g1[3] = {1.f, c1, s1};
    float g2[3] = {1.f, c2, s2};
    float P[27];
#pragma unroll
    for (int m0 = 0; m0 < 3; m0++) {
#pragma unroll
        for (int m1 = 0; m1 < 3; m1++) {
            float p01 = g0[m0] * g1[m1];
#pragma unroll
            for (int m2 = 0; m2 < 3; m2++)
                P[(m0 * 3 + m1) * 3 + m2] = p01 * g2[m2];
        }
    }

    // ---- wait for precompute, then load T ----
    pdl_wait();
    for (int i = tid; i < 540; i += 256) Ts[i] = d_Tp[i];
    __syncthreads();

    unsigned long long acc[10];
#pragma unroll
    for (int q = 0; q < 10; q++) acc[q] = 0ull;

    unsigned tbase = (unsigned)__cvta_generic_to_shared(Ts);
#pragma unroll
    for (int mx = 0; mx < 27; mx++) {
        unsigned long long p2 = pk2(P[mx]);
        unsigned ra = tbase + mx * 80;
#pragma unroll
        for (int q = 0; q < 5; q++) {
            unsigned long long t0, t1;
            asm volatile("ld.shared.v2.b64 {%0,%1}, [%2];"
                         : "=l"(t0), "=l"(t1) : "r"(ra + q * 16));
            acc[2 * q]     = fma2(p2, t0, acc[2 * q]);
            acc[2 * q + 1] = fma2(p2, t1, acc[2 * q + 1]);
        }
    }

#pragma unroll
    for (int q = 0; q < 5; q++) {
        float l0, h0v, l1, h1v;
        asm("mov.b64 {%0,%1}, %2;" : "=f"(l0), "=f"(h0v) : "l"(acc[2 * q]));
        asm("mov.b64 {%0,%1}, %2;" : "=f"(l1), "=f"(h1v) : "l"(acc[2 * q + 1]));
        d_S4[((size_t)t * 5 + q) * B_SZ + b] = make_float4(l0, h0v, l1, h1v);
    }
}

// ---------------------------------------------------------------------------
// Phase 2 (PDL): recurrence with cp.async-staged S (S is L2-hot).
// ---------------------------------------------------------------------------
__global__ void __launch_bounds__(64) phase2_kernel(float* __restrict__ out) {
    __shared__ __align__(16) float4 sbuf[8][5][64];   // 40KB
    const int tid = threadIdx.x;
    const int b = blockIdx.x * 64 + tid;

    pdl_wait();

#pragma unroll
    for (int t = 0; t < 7; t++) {
#pragma unroll
        for (int q = 0; q < 5; q++)
            cpa16(&sbuf[t][q][tid], &d_S4[((size_t)t * 5 + q) * B_SZ + b]);
        asm volatile("cp.async.commit_group;" ::: "memory");
    }

    float h0 = 0.f, h1 = 0.f;
#pragma unroll
    for (int t = 0; t < T_SZ; t++) {
        asm volatile("cp.async.wait_group 6;" ::: "memory");
        float4 v[5];
#pragma unroll
        for (int q = 0; q < 5; q++) v[q] = sbuf[t & 7][q][tid];

        if (t + 7 < T_SZ) {
#pragma unroll
            for (int q = 0; q < 5; q++)
                cpa16(&sbuf[(t + 7) & 7][q][tid],
                      &d_S4[((size_t)(t + 7) * 5 + q) * B_SZ + b]);
        }
        asm volatile("cp.async.commit_group;" ::: "memory");

        float Sc[20];
#pragma unroll
        for (int q = 0; q < 5; q++) {
            Sc[4 * q + 0] = v[q].x;
            Sc[4 * q + 1] = v[q].y;
            Sc[4 * q + 2] = v[q].z;
            Sc[4 * q + 3] = v[q].w;
        }
        float sh0, ch0, sh1, ch1;
        __sincosf(h0, &sh0, &ch0);
        __sincosf(h1, &sh1, &ch1);
        float Q[9];
        Q[0] = 1.f;        Q[1] = ch1;        Q[2] = sh1;
        Q[3] = ch0;        Q[4] = ch0 * ch1;  Q[5] = ch0 * sh1;
        Q[6] = sh0;        Q[7] = sh0 * ch1;  Q[8] = sh0 * sh1;
        float a0 = 0.f, a1 = 0.f;
#pragma unroll
        for (int mh = 0; mh < 9; mh++) {
            a0 += Sc[2 * mh] * Q[mh];
            a1 += Sc[2 * mh + 1] * Q[mh];
        }
        h0 = a0;
        h1 = a1;
    }

    // Readout
    float To[9];
#pragma unroll
    for (int i = 0; i < 9; i++) To[i] = d_To[i];
    float sh0, ch0, sh1, ch1;
    __sincosf(h0, &sh0, &ch0);
    __sincosf(h1, &sh1, &ch1);
    float Q[9] = {1.f, ch1, sh1, ch0, ch0 * ch1, ch0 * sh1,
                  sh0, sh0 * ch1, sh0 * sh1};
    float r = 0.f;
#pragma unroll
    for (int m = 0; m < 9; m++) r += To[m] * Q[m];
    out[b] = r;
}

// ---------------------------------------------------------------------------
extern "C" void kernel_launch(void* const* d_in, const int* in_sizes, int n_in,
                              void* d_out, int out_size) {
    const float* x_seq = nullptr;
    const float* w_rec = nullptr;
    const float* w_out = nullptr;
    for (int i = 0; i < n_in; i++) {
        if (in_sizes[i] == T_SZ * B_SZ * 3) x_seq = (const float*)d_in[i];
        else if (in_sizes[i] == 30)         w_rec = (const float*)d_in[i];
        else if (in_sizes[i] == 12)         w_out = (const float*)d_in[i];
    }
    float* out = (float*)d_out;

    precompute_kernel<<<1, 1024>>>(w_rec, w_out);

    {
        cudaLaunchConfig_t cfg = {};
        cfg.gridDim = dim3((T_SZ * B_SZ) / 256);
        cfg.blockDim = dim3(256);
        cudaLaunchAttribute attr[1];
        attr[0].id = cudaLaunchAttributeProgrammaticStreamSerialization;
        attr[0].val.programmaticStreamSerializationAllowed = 1;
        cfg.attrs = attr;
        cfg.numAttrs = 1;
        cfg.stream = 0;
        cudaLaunchKernelEx(&cfg, phase1_kernel, x_seq);
    }
    {
        cudaLaunchConfig_t cfg = {};
        cfg.gridDim = dim3(B_SZ / 64);
        cfg.blockDim = dim3(64);
        cudaLaunchAttribute attr[1];
        attr[0].id = cudaLaunchAttributeProgrammaticStreamSerialization;
        attr[0].val.programmaticStreamSerializationAllowed = 1;
        cfg.attrs = attr;
        cfg.numAttrs = 1;
        cfg.stream = 0;
        cudaLaunchKernelEx(&cfg, phase2_kernel, out);
    }
}

// round 9
// speedup vs baseline: 4.4630x; 1.1946x over previous
#include <cuda_runtime.h>

#define B_SZ 8192
#define T_SZ 32

// Static device scratch
__device__ float d_Tp[27 * 20];                 // [mx][k], k = mh*2+j, pads 0
__device__ float d_To[9];                       // readout tensor
__device__ float4 d_S4[T_SZ * 5 * B_SZ];        // [t][q][b] float4 (21MB)

__device__ __forceinline__ float2 cmul(float2 a, float2 b) {
    return make_float2(a.x * b.x - a.y * b.y, a.x * b.y + a.y * b.x);
}
__device__ __forceinline__ unsigned long long fma2(unsigned long long a,
                                                   unsigned long long b,
                                                   unsigned long long c) {
    unsigned long long d;
    asm("fma.rn.f32x2 %0, %1, %2, %3;" : "=l"(d) : "l"(a), "l"(b), "l"(c));
    return d;
}
__device__ __forceinline__ unsigned long long pk2(float x) {
    unsigned long long r;
    asm("mov.b64 %0, {%1, %1};" : "=l"(r) : "f"(x));
    return r;
}
__device__ __forceinline__ void cpa16(void* smem, const void* gmem) {
    unsigned s = (unsigned)__cvta_generic_to_shared(smem);
    asm volatile("cp.async.cg.shared.global [%0], [%1], 16;"
                 :: "r"(s), "l"(gmem) : "memory");
}
__device__ __forceinline__ void pdl_trigger() {
    asm volatile("griddepcontrol.launch_dependents;");
}
__device__ __forceinline__ void pdl_wait() {
    asm volatile("griddepcontrol.wait;" ::: "memory");
}

// ---------------------------------------------------------------------------
// Precompute, xmask-split: 9 blocks x 256 threads.
//   Blocks 0..7: build U redundantly (cheap), then compute ONLY the M-
//                diagonals M_j[u][u^xm] for xm in [4*blk, 4*blk+4) and project
//                the corresponding T entries. Zero cross-block dependency.
//   Block 8:     readout tensor To.
// ---------------------------------------------------------------------------
__global__ void __launch_bounds__(256) precompute_kernel(const float* __restrict__ wrec,
                                                         const float* __restrict__ wout) {
    pdl_trigger();
    const int tid = threadIdx.x;
    const int blk = blockIdx.x;

    // ================= block 8: readout tensor =================
    if (blk == 8) {
        if (tid < 9) {
            int m = tid;
            float2 V[4][4];
#pragma unroll
            for (int c2 = 0; c2 < 4; c2++)
#pragma unroll
                for (int r2 = 0; r2 < 4; r2++)
                    V[c2][r2] = make_float2(c2 == r2 ? 1.f : 0.f, 0.f);
#pragma unroll
            for (int l = 0; l < 2; l++) {
#pragma unroll
                for (int w = 0; w < 2; w++) {
                    float phi = wout[(l * 2 + w) * 3 + 0];
                    float th  = wout[(l * 2 + w) * 3 + 1];
                    float om  = wout[(l * 2 + w) * 3 + 2];
                    float s, c, sa, ca, sb, cb;
                    __sincosf(0.5f * th, &s, &c);
                    __sincosf(0.5f * (phi + om), &sa, &ca);
                    __sincosf(0.5f * (phi - om), &sb, &cb);
                    float2 r00 = make_float2( c * ca, -c * sa);
                    float2 r01 = make_float2(-s * cb, -s * sb);
                    float2 r10 = make_float2( s * cb, -s * sb);
                    float2 r11 = make_float2( c * ca,  c * sa);
                    int mask = 1 << (1 - w);
#pragma unroll
                    for (int col = 0; col < 4; col++) {
#pragma unroll
                        for (int i0 = 0; i0 < 4; i0++) {
                            if (i0 & mask) continue;
                            int i1 = i0 | mask;
                            float2 a0 = V[col][i0], a1 = V[col][i1];
                            float2 n0 = cmul(r00, a0), u01 = cmul(r01, a1);
                            n0.x += u01.x; n0.y += u01.y;
                            float2 n1 = cmul(r10, a0), u11 = cmul(r11, a1);
                            n1.x += u11.x; n1.y += u11.y;
                            V[col][i0] = n0;
                            V[col][i1] = n1;
                        }
                    }
                }
#pragma unroll
                for (int w = 0; w < 2; w++) {
                    int cm = 1 << (1 - w), tm = 1 << (1 - ((w + 1) & 1));
#pragma unroll
                    for (int col = 0; col < 4; col++)
#pragma unroll
                        for (int row = 0; row < 4; row++)
                            if ((row & cm) && !(row & tm)) {
                                float2 a = V[col][row], b2 = V[col][row | tm];
                                V[col][row] = b2;
                                V[col][row | tm] = a;
                            }
                }
            }
            float Mo[4][4];
#pragma unroll
            for (int s = 0; s < 4; s++)
#pragma unroll
                for (int t = 0; t < 4; t++) {
                    float acc = 0.f;
#pragma unroll
                    for (int k = 0; k < 4; k++) {
                        float2 vs = V[s][k], vt = V[t][k];
                        float re = vs.x * vt.x + vs.y * vt.y;
                        acc += ((k >> 1) & 1) ? -re : re;
                    }
                    Mo[s][t] = acc;
                }
            int d0 = m / 3, d1 = m % 3;
            int emask = (d0 == 1 ? 2 : 0) | (d1 == 1 ? 1 : 0);
            int xmask = (d0 == 2 ? 2 : 0) | (d1 == 2 ? 1 : 0);
            float sum = 0.f;
#pragma unroll
            for (int u = 0; u < 4; u++) {
                float sgn = (__popc(u & emask) & 1) ? -1.f : 1.f;
                sum += sgn * Mo[u][u ^ xmask];
            }
            d_To[m] = sum * 0.25f;
        }
        return;
    }

    // ================= blocks 0..7: U + M-diagonals + T slice =================
    __shared__ float2 G[10][4];
    __shared__ float UsR[32][33];
    __shared__ float UsI[32][33];
    __shared__ float sdiag[8][32];     // [wid = j*4+xmi][u]

    if (tid < 10) {
        float phi = wrec[tid * 3 + 0];
        float th  = wrec[tid * 3 + 1];
        float om  = wrec[tid * 3 + 2];
        float s, c, sa, ca, sb, cb;
        __sincosf(0.5f * th, &s, &c);
        __sincosf(0.5f * (phi + om), &sa, &ca);
        __sincosf(0.5f * (phi - om), &sb, &cb);
        G[tid][0] = make_float2( c * ca, -c * sa);
        G[tid][1] = make_float2(-s * cb, -s * sb);
        G[tid][2] = make_float2( s * cb, -s * sb);
        G[tid][3] = make_float2( c * ca,  c * sa);
    }
    // U = I (4 entries/thread)
#pragma unroll
    for (int r = 0; r < 4; r++) {
        int idx = r * 256 + tid;
        int row = idx >> 5, col = idx & 31;
        UsR[row][col] = (row == col) ? 1.f : 0.f;
        UsI[row][col] = 0.f;
    }
    __syncthreads();

#pragma unroll
    for (int l = 0; l < 2; l++) {
#pragma unroll
        for (int w = 0; w < 5; w++) {
            int mask = 1 << (4 - w);
            int low = mask - 1;
            float2 r00 = G[l * 5 + w][0], r01 = G[l * 5 + w][1];
            float2 r10 = G[l * 5 + w][2], r11 = G[l * 5 + w][3];
#pragma unroll
            for (int r = 0; r < 2; r++) {
                int idx = r * 256 + tid;
                int col = idx & 31, p = idx >> 5;   // p = 0..15
                int i0 = ((p & ~low) << 1) | (p & low);
                int i1 = i0 | mask;
                float2 a0 = make_float2(UsR[i0][col], UsI[i0][col]);
                float2 a1 = make_float2(UsR[i1][col], UsI[i1][col]);
                float2 n0 = cmul(r00, a0), u01 = cmul(r01, a1);
                n0.x += u01.x; n0.y += u01.y;
                float2 n1 = cmul(r10, a0), u11 = cmul(r11, a1);
                n1.x += u11.x; n1.y += u11.y;
                UsR[i0][col] = n0.x; UsI[i0][col] = n0.y;
                UsR[i1][col] = n1.x; UsI[i1][col] = n1.y;
            }
            __syncthreads();
        }
        // CNOT ring (range l+1) fused into one permutation
        {
            float vr[4], vi[4];
            int drow[4], dcol[4];
#pragma unroll
            for (int r = 0; r < 4; r++) {
                int idx = r * 256 + tid;
                int row = idx >> 5, col = idx & 31;
                int rr = l + 1;
                int j = row;
#pragma unroll
                for (int w = 4; w >= 0; w--) {
                    int cm = 1 << (4 - w);
                    int tm = 1 << (4 - ((w + rr) % 5));
                    if (j & cm) j ^= tm;
                }
                vr[r] = UsR[j][col];
                vi[r] = UsI[j][col];
                drow[r] = row; dcol[r] = col;
            }
            __syncthreads();
#pragma unroll
            for (int r = 0; r < 4; r++) {
                UsR[drow[r]][dcol[r]] = vr[r];
                UsI[drow[r]][dcol[r]] = vi[r];
            }
            __syncthreads();
        }
    }

    // M-diagonals: thread (j, xmi, u) computes M_j[u][u^xm]
    {
        int j   = tid >> 7;          // 0..1
        int xmi = (tid >> 5) & 3;    // 0..3
        int u   = tid & 31;
        int xm  = blk * 4 + xmi;
        int v   = u ^ xm;
        float acc = 0.f;
#pragma unroll
        for (int k = 0; k < 32; k++) {
            float re = UsR[k][u] * UsR[k][v] + UsI[k][u] * UsI[k][v];
            int sbit = (j ? k : (k >> 1)) & 1;
            acc += sbit ? -re : re;
        }
        sdiag[tid >> 5][u] = acc;
    }
    __syncthreads();

    // T slice: warp wid = (j, xmi); lane = emask index over complement bits
    {
        int wid = tid >> 5;          // 0..7
        int lid = tid & 31;
        int j   = wid >> 2;
        int xm  = blk * 4 + (wid & 3);
        int C   = (~xm) & 31;
        int nE  = 1 << (5 - __popc(xm));
        if (lid < nE) {
            // distribute bits of lid into set-bit positions of C
            int e = 0, rem = lid;
#pragma unroll
            for (int p = 0; p < 5; p++) {
                if (C & (1 << p)) {
                    if (rem & 1) e |= 1 << p;
                    rem >>= 1;
                }
            }
            float sum = 0.f;
#pragma unroll
            for (int u = 0; u < 32; u++) {
                float sgn = (__popc(u & e) & 1) ? -1.f : 1.f;
                sum += sgn * sdiag[wid][u];
            }
            // m from trits: bit p of xm -> trit 2, bit p of e -> trit 1
            int m = 0, p3 = 1;
#pragma unroll
            for (int p = 0; p < 5; p++) {
                int t3 = (xm & (1 << p)) ? 2 : ((e & (1 << p)) ? 1 : 0);
                m += t3 * p3;
                p3 *= 3;
            }
            d_Tp[(m / 9) * 20 + (m % 9) * 2 + j] = sum * (1.f / 32.f);
        }
    }

    // zero pads (block 0)
    if (blk == 0 && tid < 54) {
        d_Tp[(tid >> 1) * 20 + 18 + (tid & 1)] = 0.f;
    }
}

// ---------------------------------------------------------------------------
// Phase 1 (PDL): T-independent prework before griddepcontrol.wait.
// ---------------------------------------------------------------------------
__global__ void __launch_bounds__(256) phase1_kernel(const float* __restrict__ x_seq) {
    __shared__ __align__(16) float Ts[27 * 20];
    const int tid = threadIdx.x;

    int e = blockIdx.x * 256 + tid;
    int b = e & (B_SZ - 1);
    int t = e >> 13;

    // ---- prework (overlaps with precompute) ----
    const float* xp = x_seq + ((size_t)t * B_SZ + b) * 3;
    float x0 = xp[0], x1 = xp[1], x2 = xp[2];
    float s0, c0, s1, c1, s2, c2;
    __sincosf(x0, &s0, &c0);
    __sincosf(x1, &s1, &c1);
    __sincosf(x2, &s2, &c2);
    float g0[3] = {1.f, c0, s0};
    float g1[3] = {1.f, c1, s1};
    float g2[3] = {1.f, c2, s2};
    float P[27];
#pragma unroll
    for (int m0 = 0; m0 < 3; m0++) {
#pragma unroll
        for (int m1 = 0; m1 < 3; m1++) {
            float p01 = g0[m0] * g1[m1];
#pragma unroll
            for (int m2 = 0; m2 < 3; m2++)
                P[(m0 * 3 + m1) * 3 + m2] = p01 * g2[m2];
        }
    }

    pdl_wait();
    for (int i = tid; i < 540; i += 256) Ts[i] = d_Tp[i];
    __syncthreads();

    unsigned long long acc[10];
#pragma unroll
    for (int q = 0; q < 10; q++) acc[q] = 0ull;

    unsigned tbase = (unsigned)__cvta_generic_to_shared(Ts);
#pragma unroll
    for (int mx = 0; mx < 27; mx++) {
        unsigned long long p2 = pk2(P[mx]);
        unsigned ra = tbase + mx * 80;
#pragma unroll
        for (int q = 0; q < 5; q++) {
            unsigned long long t0, t1;
            asm volatile("ld.shared.v2.b64 {%0,%1}, [%2];"
                         : "=l"(t0), "=l"(t1) : "r"(ra + q * 16));
            acc[2 * q]     = fma2(p2, t0, acc[2 * q]);
            acc[2 * q + 1] = fma2(p2, t1, acc[2 * q + 1]);
        }
    }

#pragma unroll
    for (int q = 0; q < 5; q++) {
        float l0, h0v, l1, h1v;
        asm("mov.b64 {%0,%1}, %2;" : "=f"(l0), "=f"(h0v) : "l"(acc[2 * q]));
        asm("mov.b64 {%0,%1}, %2;" : "=f"(l1), "=f"(h1v) : "l"(acc[2 * q + 1]));
        d_S4[((size_t)t * 5 + q) * B_SZ + b] = make_float4(l0, h0v, l1, h1v);
    }
}

// ---------------------------------------------------------------------------
// Phase 2 (PDL): recurrence with cp.async-staged S (L2-hot).
// ---------------------------------------------------------------------------
__global__ void __launch_bounds__(64) phase2_kernel(float* __restrict__ out) {
    __shared__ __align__(16) float4 sbuf[8][5][64];   // 40KB
    const int tid = threadIdx.x;
    const int b = blockIdx.x * 64 + tid;

    pdl_wait();

#pragma unroll
    for (int t = 0; t < 7; t++) {
#pragma unroll
        for (int q = 0; q < 5; q++)
            cpa16(&sbuf[t][q][tid], &d_S4[((size_t)t * 5 + q) * B_SZ + b]);
        asm volatile("cp.async.commit_group;" ::: "memory");
    }

    float h0 = 0.f, h1 = 0.f;
#pragma unroll
    for (int t = 0; t < T_SZ; t++) {
        asm volatile("cp.async.wait_group 6;" ::: "memory");
        float4 v[5];
#pragma unroll
        for (int q = 0; q < 5; q++) v[q] = sbuf[t & 7][q][tid];

        if (t + 7 < T_SZ) {
#pragma unroll
            for (int q = 0; q < 5; q++)
                cpa16(&sbuf[(t + 7) & 7][q][tid],
                      &d_S4[((size_t)(t + 7) * 5 + q) * B_SZ + b]);
        }
        asm volatile("cp.async.commit_group;" ::: "memory");

        float Sc[20];
#pragma unroll
        for (int q = 0; q < 5; q++) {
            Sc[4 * q + 0] = v[q].x;
            Sc[4 * q + 1] = v[q].y;
            Sc[4 * q + 2] = v[q].z;
            Sc[4 * q + 3] = v[q].w;
        }
        float sh0, ch0, sh1, ch1;
        __sincosf(h0, &sh0, &ch0);
        __sincosf(h1, &sh1, &ch1);
        float Q[9];
        Q[0] = 1.f;        Q[1] = ch1;        Q[2] = sh1;
        Q[3] = ch0;        Q[4] = ch0 * ch1;  Q[5] = ch0 * sh1;
        Q[6] = sh0;        Q[7] = sh0 * ch1;  Q[8] = sh0 * sh1;
        float a0 = 0.f, a1 = 0.f;
#pragma unroll
        for (int mh = 0; mh < 9; mh++) {
            a0 += Sc[2 * mh] * Q[mh];
            a1 += Sc[2 * mh + 1] * Q[mh];
        }
        h0 = a0;
        h1 = a1;
    }

    // Readout
    float To[9];
#pragma unroll
    for (int i = 0; i < 9; i++) To[i] = d_To[i];
    float sh0, ch0, sh1, ch1;
    __sincosf(h0, &sh0, &ch0);
    __sincosf(h1, &sh1, &ch1);
    float Q[9] = {1.f, ch1, sh1, ch0, ch0 * ch1, ch0 * sh1,
                  sh0, sh0 * ch1, sh0 * sh1};
    float r = 0.f;
#pragma unroll
    for (int m = 0; m < 9; m++) r += To[m] * Q[m];
    out[b] = r;
}

// ---------------------------------------------------------------------------
extern "C" void kernel_launch(void* const* d_in, const int* in_sizes, int n_in,
                              void* d_out, int out_size) {
    const float* x_seq = nullptr;
    const float* w_rec = nullptr;
    const float* w_out = nullptr;
    for (int i = 0; i < n_in; i++) {
        if (in_sizes[i] == T_SZ * B_SZ * 3) x_seq = (const float*)d_in[i];
        else if (in_sizes[i] == 30)         w_rec = (const float*)d_in[i];
        else if (in_sizes[i] == 12)         w_out = (const float*)d_in[i];
    }
    float* out = (float*)d_out;

    precompute_kernel<<<9, 256>>>(w_rec, w_out);

    {
        cudaLaunchConfig_t cfg = {};
        cfg.gridDim = dim3((T_SZ * B_SZ) / 256);
        cfg.blockDim = dim3(256);
        cudaLaunchAttribute attr[1];
        attr[0].id = cudaLaunchAttributeProgrammaticStreamSerialization;
        attr[0].val.programmaticStreamSerializationAllowed = 1;
        cfg.attrs = attr;
        cfg.numAttrs = 1;
        cfg.stream = 0;
        cudaLaunchKernelEx(&cfg, phase1_kernel, x_seq);
    }
    {
        cudaLaunchConfig_t cfg = {};
        cfg.gridDim = dim3(B_SZ / 64);
        cfg.blockDim = dim3(64);
        cudaLaunchAttribute attr[1];
        attr[0].id = cudaLaunchAttributeProgrammaticStreamSerialization;
        attr[0].val.programmaticStreamSerializationAllowed = 1;
        cfg.attrs = attr;
        cfg.numAttrs = 1;
        cfg.stream = 0;
        cudaLaunchKernelEx(&cfg, phase2_kernel, out);
    }
}